// round 5
// baseline (speedup 1.0000x reference)
#include <cuda_runtime.h>

#define NB 64
#define LC 4096
#define HD 768
#define PD 128
#define BUDGETF 200.0f
#define NCHUNK 32                 // LC / 128 chunks per batch

// Scratch (allocation-free rule: __device__ globals)
__device__ float d_U[NB * HD];      // u_b = Wc @ q_b
__device__ float d_qbias[NB];       // q_b . bc
__device__ int   d_len[NB];         // valid context length per batch
__device__ float d_s[NB * LC];      // match scores (only [0,len) valid)

// ---------------------------------------------------------------------------
// Kernel 1 (fused): q_b = qr_b @ Wq + bq ; u_b = Wc @ q_b ; qbias ; len
// 512 threads, grid 64. All global reads coalesced.
// ---------------------------------------------------------------------------
__global__ void __launch_bounds__(512) proj_kernel(const float* __restrict__ qr,
                                                   const float* __restrict__ Wq,
                                                   const float* __restrict__ bq,
                                                   const float* __restrict__ Wc,
                                                   const float* __restrict__ bc,
                                                   const int* __restrict__ mask) {
    int b = blockIdx.x;
    __shared__ float sh_qr[HD];
    __shared__ float sh_part[512];
    __shared__ float sh_q[PD];
    __shared__ int sh_cnt[16];
    int tid = threadIdx.x;
    int warp = tid >> 5, lane = tid & 31;

    for (int i = tid; i < HD; i += 512) sh_qr[i] = qr[b * HD + i];

    // len[b] = sum(mask[b,:])
    int cnt = 0;
    for (int i = tid; i < LC; i += 512) cnt += mask[b * LC + i];
    #pragma unroll
    for (int off = 16; off; off >>= 1) cnt += __shfl_xor_sync(0xffffffffu, cnt, off);
    if (lane == 0) sh_cnt[warp] = cnt;
    __syncthreads();
    if (tid == 0) {
        int t = 0;
        #pragma unroll
        for (int w = 0; w < 16; w++) t += sh_cnt[w];
        d_len[b] = t;
    }

    // Stage A: q[p] = sum_h qr[h] * Wq[h,p] + bq[p]  (4 h-slices x 128 p)
    int p = tid & 127;
    int slice = tid >> 7;
    int h0 = slice * (HD / 4);
    float a0 = 0.f, a1 = 0.f, a2 = 0.f, a3 = 0.f;
    #pragma unroll 4
    for (int h = h0; h < h0 + HD / 4; h += 4) {
        a0 = fmaf(sh_qr[h + 0], Wq[(h + 0) * PD + p], a0);
        a1 = fmaf(sh_qr[h + 1], Wq[(h + 1) * PD + p], a1);
        a2 = fmaf(sh_qr[h + 2], Wq[(h + 2) * PD + p], a2);
        a3 = fmaf(sh_qr[h + 3], Wq[(h + 3) * PD + p], a3);
    }
    sh_part[tid] = (a0 + a1) + (a2 + a3);
    __syncthreads();

    if (tid < PD) {
        sh_q[tid] = sh_part[tid] + sh_part[PD + tid] + sh_part[2 * PD + tid]
                  + sh_part[3 * PD + tid] + bq[tid];
    }
    __syncthreads();

    // qbias = q . bc
    if (tid < 32) {
        float v = 0.f;
        #pragma unroll
        for (int k = 0; k < 4; k++)
            v = fmaf(sh_q[tid + 32 * k], bc[tid + 32 * k], v);
        #pragma unroll
        for (int off = 16; off; off >>= 1)
            v += __shfl_xor_sync(0xffffffffu, v, off);
        if (tid == 0) d_qbias[b] = v;
    }

    // Stage B: u[h] = Wc[h,:] . q   (warp per h, lanes over p: coalesced)
    for (int h = warp; h < HD; h += 16) {
        const float* wr = Wc + (size_t)h * PD;
        float acc = wr[lane] * sh_q[lane];
        acc = fmaf(wr[lane + 32], sh_q[lane + 32], acc);
        acc = fmaf(wr[lane + 64], sh_q[lane + 64], acc);
        acc = fmaf(wr[lane + 96], sh_q[lane + 96], acc);
        #pragma unroll
        for (int off = 16; off; off >>= 1)
            acc += __shfl_xor_sync(0xffffffffu, acc, off);
        if (lane == 0) d_U[b * HD + h] = acc;
    }
}

// ---------------------------------------------------------------------------
// Kernel 2: s[b,j] = ctx[b,j,:].u_b + qbias for j < len[b].
// Grid-stride persistent blocks; u held in registers per chunk.
// ---------------------------------------------------------------------------
#define SCORE_BLOCKS 1184

__global__ void __launch_bounds__(256) score_kernel(const float* __restrict__ ctx) {
    __shared__ float sh_u[HD];
    int tid = threadIdx.x;
    int warp = tid >> 5, lane = tid & 31;

    for (int c = blockIdx.x; c < NB * NCHUNK; c += gridDim.x) {
        int b = c >> 5;
        int j0 = (c & 31) * 128;
        int len = d_len[b];
        if (j0 >= len) continue;        // uniform across block

        __syncthreads();                // protect sh_u from previous iteration
        for (int i = tid; i < HD; i += 256) sh_u[i] = d_U[b * HD + i];
        __syncthreads();

        int nv = min(128, len - j0);
        float bias = d_qbias[b];
        const float4* u4 = (const float4*)sh_u;

        // hoist this lane's slice of u into registers (reused over 16 rows)
        float4 w0 = u4[lane +   0], w1 = u4[lane +  32], w2 = u4[lane +  64];
        float4 w3 = u4[lane +  96], w4 = u4[lane + 128], w5 = u4[lane + 160];

        for (int r = warp; r < nv; r += 8) {
            int j = j0 + r;
            const float4* row = (const float4*)(ctx + ((size_t)b * LC + j) * HD);
            float4 v0 = __ldcs(row + lane +   0);
            float4 v1 = __ldcs(row + lane +  32);
            float4 v2 = __ldcs(row + lane +  64);
            float4 v3 = __ldcs(row + lane +  96);
            float4 v4 = __ldcs(row + lane + 128);
            float4 v5 = __ldcs(row + lane + 160);
            float acc = v0.x * w0.x;
            acc = fmaf(v0.y, w0.y, acc); acc = fmaf(v0.z, w0.z, acc); acc = fmaf(v0.w, w0.w, acc);
            acc = fmaf(v1.x, w1.x, acc); acc = fmaf(v1.y, w1.y, acc); acc = fmaf(v1.z, w1.z, acc); acc = fmaf(v1.w, w1.w, acc);
            acc = fmaf(v2.x, w2.x, acc); acc = fmaf(v2.y, w2.y, acc); acc = fmaf(v2.z, w2.z, acc); acc = fmaf(v2.w, w2.w, acc);
            acc = fmaf(v3.x, w3.x, acc); acc = fmaf(v3.y, w3.y, acc); acc = fmaf(v3.z, w3.z, acc); acc = fmaf(v3.w, w3.w, acc);
            acc = fmaf(v4.x, w4.x, acc); acc = fmaf(v4.y, w4.y, acc); acc = fmaf(v4.z, w4.z, acc); acc = fmaf(v4.w, w4.w, acc);
            acc = fmaf(v5.x, w5.x, acc); acc = fmaf(v5.y, w5.y, acc); acc = fmaf(v5.z, w5.z, acc); acc = fmaf(v5.w, w5.w, acc);
            #pragma unroll
            for (int off = 16; off; off >>= 1)
                acc += __shfl_xor_sync(0xffffffffu, acc, off);
            if (lane == 0) d_s[b * LC + j] = acc + bias;
        }
    }
}

// ---------------------------------------------------------------------------
// Kernel 3: per-batch budget projection — 8-ary bisection (7 candidates per
// reduction round, 10 rounds) + fused gather/scatter.
// ---------------------------------------------------------------------------
__device__ __forceinline__ float clip01(float v) {
    return fminf(fmaxf(v, 0.f), 1.f);
}

__global__ void __launch_bounds__(256) budget_kernel(const int* __restrict__ qe_arr,
                                                     float* __restrict__ out) {
    int b = blockIdx.x;
    const int NT = 256;
    __shared__ float sh_s[LC];
    __shared__ float redf[8 * 7];
    __shared__ float sh_tot[8];
    int tid = threadIdx.x, warp = tid >> 5, lane = tid & 31;
    int len = d_len[b];

    // load s[0,len) into smem (gather needs random access)
    const float4* src = (const float4*)(d_s + b * LC);
    int n4 = (len + 3) >> 2;
    for (int i = tid; i < n4; i += NT) ((float4*)sh_s)[i] = src[i];
    __syncthreads();

    // register-resident values; invalid -> -1e5 (contributes 0, never max)
    float v[16];
    #pragma unroll
    for (int k = 0; k < 16; k++) {
        int i = tid + k * NT;
        v[k] = (i < len) ? sh_s[i] : -100000.0f;
    }

    // local max and z_sum(0), fused block reduce
    float mx = -100000.0f, sum0 = 0.f;
    #pragma unroll
    for (int k = 0; k < 16; k++) {
        mx = fmaxf(mx, v[k]);
        sum0 += clip01(v[k]);
    }
    {
        #pragma unroll
        for (int off = 16; off; off >>= 1) {
            mx   = fmaxf(mx, __shfl_xor_sync(0xffffffffu, mx, off));
            sum0 += __shfl_xor_sync(0xffffffffu, sum0, off);
        }
        if (lane == 0) { redf[warp * 2] = mx; redf[warp * 2 + 1] = sum0; }
        __syncthreads();
        if (tid == 0) {
            float a = redf[0], s = redf[1];
            #pragma unroll
            for (int w = 1; w < 8; w++) {
                a = fmaxf(a, redf[w * 2]);
                s += redf[w * 2 + 1];
            }
            sh_tot[0] = a; sh_tot[1] = s;
        }
        __syncthreads();
        mx = sh_tot[0]; sum0 = sh_tot[1];
    }

    float tau = 0.f;
    if (sum0 > BUDGETF) {
        float lo = 0.f, hi = mx;
        for (int it = 0; it < 10; it++) {
            float step = (hi - lo) * 0.125f;
            float part[7];
            #pragma unroll
            for (int c = 0; c < 7; c++) part[c] = 0.f;
            #pragma unroll
            for (int k = 0; k < 16; k++) {
                float x = v[k] - lo;
                #pragma unroll
                for (int c = 0; c < 7; c++)
                    part[c] += clip01(x - (c + 1) * step);
            }
            #pragma unroll
            for (int c = 0; c < 7; c++) {
                #pragma unroll
                for (int off = 16; off; off >>= 1)
                    part[c] += __shfl_xor_sync(0xffffffffu, part[c], off);
            }
            if (lane == 0) {
                #pragma unroll
                for (int c = 0; c < 7; c++) redf[warp * 7 + c] = part[c];
            }
            __syncthreads();
            if (tid < 7) {
                float t = redf[tid];
                #pragma unroll
                for (int w = 1; w < 8; w++) t += redf[w * 7 + tid];
                sh_tot[tid] = t;
            }
            __syncthreads();
            // S non-increasing in tau: lo = last candidate with S>BUDGET,
            // hi = first candidate with S<=BUDGET (all threads identical).
            float nlo = lo, nhi = hi;
            bool crossed = false;
            #pragma unroll
            for (int c = 0; c < 7; c++) {
                float tc = lo + (c + 1) * step;
                if (!crossed) {
                    if (sh_tot[c] > BUDGETF) nlo = tc;
                    else { nhi = tc; crossed = true; }
                }
            }
            lo = nlo; hi = nhi;
            __syncthreads();   // protect redf/sh_tot before next round
        }
        tau = 0.5f * (lo + hi);
    }

    // fused gather/scatter into token_z
    int qe = qe_arr[b];
    int clen = len - 1;
    for (int p = tid; p < LC; p += NT) {
        float r;
        if (p < qe) {
            r = 1.f;
        } else {
            int idx = p - qe + 1;                 // >= 1
            r = (idx <= clen) ? clip01(sh_s[idx] - tau) : 0.f;
        }
        out[b * LC + p] = r;
    }
}

// ---------------------------------------------------------------------------
extern "C" void kernel_launch(void* const* d_in, const int* in_sizes, int n_in,
                              void* d_out, int out_size) {
    const float* question = (const float*)d_in[0];  // [B,1,H]
    const float* context  = (const float*)d_in[1];  // [B,LC,H]
    const float* Wq       = (const float*)d_in[2];  // [H,P]
    const float* bq       = (const float*)d_in[3];  // [P]
    const float* Wc       = (const float*)d_in[4];  // [H,P]
    const float* bc       = (const float*)d_in[5];  // [P]
    const int*   maskp    = (const int*)d_in[6];    // [B,LC]
    const int*   qep      = (const int*)d_in[7];    // [B]
    float* out = (float*)d_out;                     // [B,MAXLEN]

    proj_kernel<<<NB, 512>>>(question, Wq, bq, Wc, bc, maskp);
    score_kernel<<<SCORE_BLOCKS, 256>>>(context);
    budget_kernel<<<NB, 256>>>(qep, out);
}

// round 6
// speedup vs baseline: 1.0185x; 1.0185x over previous
#include <cuda_runtime.h>

#define NB 64
#define LC 4096
#define HD 768
#define PD 128
#define BUDGETF 200.0f
#define NCHUNK 32                 // LC / 128 chunks per batch

// Scratch (allocation-free rule: __device__ globals)
__device__ float d_q[NB * PD];      // q_b = qr_b @ Wq + bq
__device__ float d_U[NB * HD];      // u_b = Wc @ q_b
__device__ float d_qbias[NB];       // q_b . bc
__device__ int   d_len[NB];         // valid context length per batch
__device__ float d_s[NB * LC];      // match scores (only [0,len) valid)

// ---------------------------------------------------------------------------
// Kernel 1a: q[b,p] = qr[b,:] . Wq[:,p] + bq[p] ; qbias[b] = q_b . bc ;
//            len[b] = sum(mask[b,:])      (round-4 version, measured fast)
// ---------------------------------------------------------------------------
__global__ void __launch_bounds__(512) qproj_kernel(const float* __restrict__ qr,
                                                    const float* __restrict__ Wq,
                                                    const float* __restrict__ bq,
                                                    const float* __restrict__ bc,
                                                    const int* __restrict__ mask) {
    int b = blockIdx.x;
    __shared__ float sh_qr[HD];
    __shared__ float sh_part[512];
    __shared__ int sh_cnt[16];
    int tid = threadIdx.x;

    for (int i = tid; i < HD; i += 512) sh_qr[i] = qr[b * HD + i];

    int cnt = 0;
    for (int i = tid; i < LC; i += 512) cnt += mask[b * LC + i];
    #pragma unroll
    for (int off = 16; off; off >>= 1) cnt += __shfl_xor_sync(0xffffffffu, cnt, off);
    if ((tid & 31) == 0) sh_cnt[tid >> 5] = cnt;
    __syncthreads();
    if (tid == 0) {
        int t = 0;
        #pragma unroll
        for (int w = 0; w < 16; w++) t += sh_cnt[w];
        d_len[b] = t;
    }

    int p = tid & 127;
    int slice = tid >> 7;            // 0..3
    int h0 = slice * (HD / 4);       // 192 rows per slice
    float a0 = 0.f, a1 = 0.f, a2 = 0.f, a3 = 0.f;
    #pragma unroll 4
    for (int h = h0; h < h0 + HD / 4; h += 4) {
        a0 = fmaf(sh_qr[h + 0], Wq[(h + 0) * PD + p], a0);
        a1 = fmaf(sh_qr[h + 1], Wq[(h + 1) * PD + p], a1);
        a2 = fmaf(sh_qr[h + 2], Wq[(h + 2) * PD + p], a2);
        a3 = fmaf(sh_qr[h + 3], Wq[(h + 3) * PD + p], a3);
    }
    sh_part[tid] = (a0 + a1) + (a2 + a3);
    __syncthreads();

    if (tid < PD) {
        float q = sh_part[tid] + sh_part[PD + tid] + sh_part[2 * PD + tid]
                + sh_part[3 * PD + tid] + bq[tid];
        d_q[b * PD + tid] = q;
        sh_part[tid] = q;
    }
    __syncthreads();

    if (tid < 32) {
        float v = 0.f;
        #pragma unroll
        for (int k = 0; k < 4; k++)
            v = fmaf(sh_part[tid + 32 * k], bc[tid + 32 * k], v);
        #pragma unroll
        for (int off = 16; off; off >>= 1)
            v += __shfl_xor_sync(0xffffffffu, v, off);
        if (tid == 0) d_qbias[b] = v;
    }
}

// ---------------------------------------------------------------------------
// Kernel 1b: u[b,h] = Wc[h,:] . q_b  (warp per h, lanes over p; grid 64x4)
// ---------------------------------------------------------------------------
__global__ void __launch_bounds__(256) uproj_kernel(const float* __restrict__ Wc) {
    int b = blockIdx.x;
    int chunk = blockIdx.y;
    __shared__ float sh_q[PD];
    int tid = threadIdx.x;
    if (tid < PD) sh_q[tid] = d_q[b * PD + tid];
    __syncthreads();

    int warp = tid >> 5, lane = tid & 31;
    for (int hh = warp; hh < HD / 4; hh += 8) {
        int h = chunk * (HD / 4) + hh;
        const float* wr = Wc + (size_t)h * PD;
        float acc = wr[lane] * sh_q[lane];
        acc = fmaf(wr[lane + 32], sh_q[lane + 32], acc);
        acc = fmaf(wr[lane + 64], sh_q[lane + 64], acc);
        acc = fmaf(wr[lane + 96], sh_q[lane + 96], acc);
        #pragma unroll
        for (int off = 16; off; off >>= 1)
            acc += __shfl_xor_sync(0xffffffffu, acc, off);
        if (lane == 0) d_U[b * HD + h] = acc;
    }
}

// ---------------------------------------------------------------------------
// Kernel 2: s[b,j] = ctx[b,j,:].u_b + qbias for j < len[b].
// Grid-stride persistent blocks; u in registers per chunk.
// ---------------------------------------------------------------------------
#define SCORE_BLOCKS 1184

__global__ void __launch_bounds__(256) score_kernel(const float* __restrict__ ctx) {
    __shared__ float sh_u[HD];
    int tid = threadIdx.x;
    int warp = tid >> 5, lane = tid & 31;

    for (int c = blockIdx.x; c < NB * NCHUNK; c += gridDim.x) {
        int b = c >> 5;
        int j0 = (c & 31) * 128;
        int len = d_len[b];
        if (j0 >= len) continue;        // uniform across block

        __syncthreads();                // protect sh_u from previous iteration
        for (int i = tid; i < HD; i += 256) sh_u[i] = d_U[b * HD + i];
        __syncthreads();

        int nv = min(128, len - j0);
        float bias = d_qbias[b];
        const float4* u4 = (const float4*)sh_u;

        float4 w0 = u4[lane +   0], w1 = u4[lane +  32], w2 = u4[lane +  64];
        float4 w3 = u4[lane +  96], w4 = u4[lane + 128], w5 = u4[lane + 160];

        for (int r = warp; r < nv; r += 8) {
            int j = j0 + r;
            const float4* row = (const float4*)(ctx + ((size_t)b * LC + j) * HD);
            float4 v0 = __ldcs(row + lane +   0);
            float4 v1 = __ldcs(row + lane +  32);
            float4 v2 = __ldcs(row + lane +  64);
            float4 v3 = __ldcs(row + lane +  96);
            float4 v4 = __ldcs(row + lane + 128);
            float4 v5 = __ldcs(row + lane + 160);
            float acc = v0.x * w0.x;
            acc = fmaf(v0.y, w0.y, acc); acc = fmaf(v0.z, w0.z, acc); acc = fmaf(v0.w, w0.w, acc);
            acc = fmaf(v1.x, w1.x, acc); acc = fmaf(v1.y, w1.y, acc); acc = fmaf(v1.z, w1.z, acc); acc = fmaf(v1.w, w1.w, acc);
            acc = fmaf(v2.x, w2.x, acc); acc = fmaf(v2.y, w2.y, acc); acc = fmaf(v2.z, w2.z, acc); acc = fmaf(v2.w, w2.w, acc);
            acc = fmaf(v3.x, w3.x, acc); acc = fmaf(v3.y, w3.y, acc); acc = fmaf(v3.z, w3.z, acc); acc = fmaf(v3.w, w3.w, acc);
            acc = fmaf(v4.x, w4.x, acc); acc = fmaf(v4.y, w4.y, acc); acc = fmaf(v4.z, w4.z, acc); acc = fmaf(v4.w, w4.w, acc);
            acc = fmaf(v5.x, w5.x, acc); acc = fmaf(v5.y, w5.y, acc); acc = fmaf(v5.z, w5.z, acc); acc = fmaf(v5.w, w5.w, acc);
            #pragma unroll
            for (int off = 16; off; off >>= 1)
                acc += __shfl_xor_sync(0xffffffffu, acc, off);
            if (lane == 0) d_s[b * LC + j] = acc + bias;
        }
    }
}

// ---------------------------------------------------------------------------
// Kernel 3: per-batch budget projection — 8-ary bisection (7 candidates per
// reduction round, 10 rounds) + fused gather/scatter.
// ---------------------------------------------------------------------------
__device__ __forceinline__ float clip01(float v) {
    return fminf(fmaxf(v, 0.f), 1.f);
}

__global__ void __launch_bounds__(256) budget_kernel(const int* __restrict__ qe_arr,
                                                     float* __restrict__ out) {
    int b = blockIdx.x;
    const int NT = 256;
    __shared__ float sh_s[LC];
    __shared__ float redf[8 * 7];
    __shared__ float sh_tot[8];
    int tid = threadIdx.x, warp = tid >> 5, lane = tid & 31;
    int len = d_len[b];

    const float4* src = (const float4*)(d_s + b * LC);
    int n4 = (len + 3) >> 2;
    for (int i = tid; i < n4; i += NT) ((float4*)sh_s)[i] = src[i];
    __syncthreads();

    float v[16];
    #pragma unroll
    for (int k = 0; k < 16; k++) {
        int i = tid + k * NT;
        v[k] = (i < len) ? sh_s[i] : -100000.0f;
    }

    float mx = -100000.0f, sum0 = 0.f;
    #pragma unroll
    for (int k = 0; k < 16; k++) {
        mx = fmaxf(mx, v[k]);
        sum0 += clip01(v[k]);
    }
    {
        #pragma unroll
        for (int off = 16; off; off >>= 1) {
            mx   = fmaxf(mx, __shfl_xor_sync(0xffffffffu, mx, off));
            sum0 += __shfl_xor_sync(0xffffffffu, sum0, off);
        }
        if (lane == 0) { redf[warp * 2] = mx; redf[warp * 2 + 1] = sum0; }
        __syncthreads();
        if (tid == 0) {
            float a = redf[0], s = redf[1];
            #pragma unroll
            for (int w = 1; w < 8; w++) {
                a = fmaxf(a, redf[w * 2]);
                s += redf[w * 2 + 1];
            }
            sh_tot[0] = a; sh_tot[1] = s;
        }
        __syncthreads();
        mx = sh_tot[0]; sum0 = sh_tot[1];
    }

    float tau = 0.f;
    if (sum0 > BUDGETF) {
        float lo = 0.f, hi = mx;
        for (int it = 0; it < 10; it++) {
            float step = (hi - lo) * 0.125f;
            float part[7];
            #pragma unroll
            for (int c = 0; c < 7; c++) part[c] = 0.f;
            #pragma unroll
            for (int k = 0; k < 16; k++) {
                float x = v[k] - lo;
                #pragma unroll
                for (int c = 0; c < 7; c++)
                    part[c] += clip01(x - (c + 1) * step);
            }
            #pragma unroll
            for (int c = 0; c < 7; c++) {
                #pragma unroll
                for (int off = 16; off; off >>= 1)
                    part[c] += __shfl_xor_sync(0xffffffffu, part[c], off);
            }
            if (lane == 0) {
                #pragma unroll
                for (int c = 0; c < 7; c++) redf[warp * 7 + c] = part[c];
            }
            __syncthreads();
            if (tid < 7) {
                float t = redf[tid];
                #pragma unroll
                for (int w = 1; w < 8; w++) t += redf[w * 7 + tid];
                sh_tot[tid] = t;
            }
            __syncthreads();
            float nlo = lo, nhi = hi;
            bool crossed = false;
            #pragma unroll
            for (int c = 0; c < 7; c++) {
                float tc = lo + (c + 1) * step;
                if (!crossed) {
                    if (sh_tot[c] > BUDGETF) nlo = tc;
                    else { nhi = tc; crossed = true; }
                }
            }
            lo = nlo; hi = nhi;
            __syncthreads();
        }
        tau = 0.5f * (lo + hi);
    }

    int qe = qe_arr[b];
    int clen = len - 1;
    for (int p = tid; p < LC; p += NT) {
        float r;
        if (p < qe) {
            r = 1.f;
        } else {
            int idx = p - qe + 1;                 // >= 1
            r = (idx <= clen) ? clip01(sh_s[idx] - tau) : 0.f;
        }
        out[b * LC + p] = r;
    }
}

// ---------------------------------------------------------------------------
extern "C" void kernel_launch(void* const* d_in, const int* in_sizes, int n_in,
                              void* d_out, int out_size) {
    const float* question = (const float*)d_in[0];  // [B,1,H]
    const float* context  = (const float*)d_in[1];  // [B,LC,H]
    const float* Wq       = (const float*)d_in[2];  // [H,P]
    const float* bq       = (const float*)d_in[3];  // [P]
    const float* Wc       = (const float*)d_in[4];  // [H,P]
    const float* bc       = (const float*)d_in[5];  // [P]
    const int*   maskp    = (const int*)d_in[6];    // [B,LC]
    const int*   qep      = (const int*)d_in[7];    // [B]
    float* out = (float*)d_out;                     // [B,MAXLEN]

    qproj_kernel<<<NB, 512>>>(question, Wq, bq, bc, maskp);
    dim3 gu(NB, 4);
    uproj_kernel<<<gu, 256>>>(Wc);
    score_kernel<<<SCORE_BLOCKS, 256>>>(context);
    budget_kernel<<<NB, 256>>>(qep, out);
}

// round 7
// speedup vs baseline: 1.1528x; 1.1319x over previous
#include <cuda_runtime.h>

#define NB 64
#define LC 4096
#define HD 768
#define PD 128
#define BUDGETF 200.0f
#define NCHUNK 32                 // LC / 128 chunks per batch

// Scratch (allocation-free rule: __device__ globals)
__device__ float d_q[NB * PD];      // q_b = qr_b @ Wq + bq
__device__ float d_U[NB * HD];      // u_b = Wc @ q_b
__device__ float d_qbias[NB];       // q_b . bc
__device__ int   d_len[NB];         // valid context length per batch
__device__ float d_tau[NB];         // solved threshold per batch
__device__ float d_s[NB * LC];      // match scores (only [0,len) valid)

// ---------------------------------------------------------------------------
// Kernel 1a: q[b,p] = qr[b,:] . Wq[:,p] + bq[p] ; qbias[b] = q_b . bc ;
//            len[b] = sum(mask[b,:])      (round-4 version, measured fast)
// ---------------------------------------------------------------------------
__global__ void __launch_bounds__(512) qproj_kernel(const float* __restrict__ qr,
                                                    const float* __restrict__ Wq,
                                                    const float* __restrict__ bq,
                                                    const float* __restrict__ bc,
                                                    const int* __restrict__ mask) {
    int b = blockIdx.x;
    __shared__ float sh_qr[HD];
    __shared__ float sh_part[512];
    __shared__ int sh_cnt[16];
    int tid = threadIdx.x;

    for (int i = tid; i < HD; i += 512) sh_qr[i] = qr[b * HD + i];

    int cnt = 0;
    for (int i = tid; i < LC; i += 512) cnt += mask[b * LC + i];
    #pragma unroll
    for (int off = 16; off; off >>= 1) cnt += __shfl_xor_sync(0xffffffffu, cnt, off);
    if ((tid & 31) == 0) sh_cnt[tid >> 5] = cnt;
    __syncthreads();
    if (tid == 0) {
        int t = 0;
        #pragma unroll
        for (int w = 0; w < 16; w++) t += sh_cnt[w];
        d_len[b] = t;
    }

    int p = tid & 127;
    int slice = tid >> 7;            // 0..3
    int h0 = slice * (HD / 4);       // 192 rows per slice
    float a0 = 0.f, a1 = 0.f, a2 = 0.f, a3 = 0.f;
    #pragma unroll 4
    for (int h = h0; h < h0 + HD / 4; h += 4) {
        a0 = fmaf(sh_qr[h + 0], Wq[(h + 0) * PD + p], a0);
        a1 = fmaf(sh_qr[h + 1], Wq[(h + 1) * PD + p], a1);
        a2 = fmaf(sh_qr[h + 2], Wq[(h + 2) * PD + p], a2);
        a3 = fmaf(sh_qr[h + 3], Wq[(h + 3) * PD + p], a3);
    }
    sh_part[tid] = (a0 + a1) + (a2 + a3);
    __syncthreads();

    if (tid < PD) {
        float q = sh_part[tid] + sh_part[PD + tid] + sh_part[2 * PD + tid]
                + sh_part[3 * PD + tid] + bq[tid];
        d_q[b * PD + tid] = q;
        sh_part[tid] = q;
    }
    __syncthreads();

    if (tid < 32) {
        float v = 0.f;
        #pragma unroll
        for (int k = 0; k < 4; k++)
            v = fmaf(sh_part[tid + 32 * k], bc[tid + 32 * k], v);
        #pragma unroll
        for (int off = 16; off; off >>= 1)
            v += __shfl_xor_sync(0xffffffffu, v, off);
        if (tid == 0) d_qbias[b] = v;
    }
}

// ---------------------------------------------------------------------------
// Kernel 1b: u[b,h] = Wc[h,:] . q_b  (warp per h, lanes over p; grid 64x4)
// ---------------------------------------------------------------------------
__global__ void __launch_bounds__(256) uproj_kernel(const float* __restrict__ Wc) {
    int b = blockIdx.x;
    int chunk = blockIdx.y;
    __shared__ float sh_q[PD];
    int tid = threadIdx.x;
    if (tid < PD) sh_q[tid] = d_q[b * PD + tid];
    __syncthreads();

    int warp = tid >> 5, lane = tid & 31;
    for (int hh = warp; hh < HD / 4; hh += 8) {
        int h = chunk * (HD / 4) + hh;
        const float* wr = Wc + (size_t)h * PD;
        float acc = wr[lane] * sh_q[lane];
        acc = fmaf(wr[lane + 32], sh_q[lane + 32], acc);
        acc = fmaf(wr[lane + 64], sh_q[lane + 64], acc);
        acc = fmaf(wr[lane + 96], sh_q[lane + 96], acc);
        #pragma unroll
        for (int off = 16; off; off >>= 1)
            acc += __shfl_xor_sync(0xffffffffu, acc, off);
        if (lane == 0) d_U[b * HD + h] = acc;
    }
}

// ---------------------------------------------------------------------------
// Kernel 2: s[b,j] = ctx[b,j,:].u_b + qbias for j < len[b].
// Grid-stride persistent blocks. EXACT round-4 inner loop (measured fast).
// ---------------------------------------------------------------------------
#define SCORE_BLOCKS 1184

__global__ void __launch_bounds__(256) score_kernel(const float* __restrict__ ctx) {
    __shared__ float sh_u[HD];
    int tid = threadIdx.x;
    int warp = tid >> 5, lane = tid & 31;

    for (int c = blockIdx.x; c < NB * NCHUNK; c += gridDim.x) {
        int b = c >> 5;
        int j0 = (c & 31) * 128;
        int len = d_len[b];
        if (j0 >= len) continue;        // uniform across block

        __syncthreads();                // protect sh_u from previous iteration
        for (int i = tid; i < HD; i += 256) sh_u[i] = d_U[b * HD + i];
        __syncthreads();

        int nv = min(128, len - j0);
        float bias = d_qbias[b];
        const float4* u4 = (const float4*)sh_u;

        for (int r = warp; r < nv; r += 8) {
            int j = j0 + r;
            const float4* row = (const float4*)(ctx + ((size_t)b * LC + j) * HD);
            float acc = 0.f;
            #pragma unroll
            for (int i = 0; i < 6; i++) {       // 192 float4 / 32 lanes
                float4 v = __ldcs(row + lane + 32 * i);
                float4 w = u4[lane + 32 * i];
                acc = fmaf(v.x, w.x, acc);
                acc = fmaf(v.y, w.y, acc);
                acc = fmaf(v.z, w.z, acc);
                acc = fmaf(v.w, w.w, acc);
            }
            #pragma unroll
            for (int off = 16; off; off >>= 1)
                acc += __shfl_xor_sync(0xffffffffu, acc, off);
            if (lane == 0) d_s[b * LC + j] = acc + bias;
        }
    }
}

// ---------------------------------------------------------------------------
// Kernel 3a: tau solve — 512 threads x 8 register values, 8 rounds of
// 7-candidate (8-ary) search. No smem s-copy; direct coalesced global loads.
// ---------------------------------------------------------------------------
__device__ __forceinline__ float clip01(float v) {
    return fminf(fmaxf(v, 0.f), 1.f);
}

__global__ void __launch_bounds__(512) tau_kernel() {
    int b = blockIdx.x;
    const int NT = 512;
    __shared__ float redf[16 * 7];
    __shared__ float sh_tot[8];
    int tid = threadIdx.x, warp = tid >> 5, lane = tid & 31;
    int len = d_len[b];
    const float* sp = d_s + b * LC;

    // register-resident values; invalid -> -1e5 (contributes 0, never max)
    float v[8];
    #pragma unroll
    for (int k = 0; k < 8; k++) {
        int i = tid + k * NT;
        v[k] = (i < len) ? sp[i] : -100000.0f;
    }

    // max and z_sum(0), fused block reduce
    float mx = -100000.0f, sum0 = 0.f;
    #pragma unroll
    for (int k = 0; k < 8; k++) {
        mx = fmaxf(mx, v[k]);
        sum0 += clip01(v[k]);
    }
    {
        #pragma unroll
        for (int off = 16; off; off >>= 1) {
            mx   = fmaxf(mx, __shfl_xor_sync(0xffffffffu, mx, off));
            sum0 += __shfl_xor_sync(0xffffffffu, sum0, off);
        }
        if (lane == 0) { redf[warp * 2] = mx; redf[warp * 2 + 1] = sum0; }
        __syncthreads();
        if (tid == 0) {
            float a = redf[0], s = redf[1];
            #pragma unroll
            for (int w = 1; w < 16; w++) {
                a = fmaxf(a, redf[w * 2]);
                s += redf[w * 2 + 1];
            }
            sh_tot[0] = a; sh_tot[1] = s;
        }
        __syncthreads();
        mx = sh_tot[0]; sum0 = sh_tot[1];
    }

    float tau = 0.f;
    if (sum0 > BUDGETF) {
        float lo = 0.f, hi = mx;
        for (int it = 0; it < 8; it++) {
            float step = (hi - lo) * 0.125f;
            float part[7];
            #pragma unroll
            for (int c = 0; c < 7; c++) part[c] = 0.f;
            #pragma unroll
            for (int k = 0; k < 8; k++) {
                float x = v[k] - lo;
                #pragma unroll
                for (int c = 0; c < 7; c++)
                    part[c] += clip01(x - (c + 1) * step);
            }
            #pragma unroll
            for (int c = 0; c < 7; c++) {
                #pragma unroll
                for (int off = 16; off; off >>= 1)
                    part[c] += __shfl_xor_sync(0xffffffffu, part[c], off);
            }
            if (lane == 0) {
                #pragma unroll
                for (int c = 0; c < 7; c++) redf[warp * 7 + c] = part[c];
            }
            __syncthreads();
            if (tid < 7) {
                float t = redf[tid];
                #pragma unroll
                for (int w = 1; w < 16; w++) t += redf[w * 7 + tid];
                sh_tot[tid] = t;
            }
            __syncthreads();
            // S non-increasing in tau: advance lo past candidates with
            // S>BUDGET; hi = first with S<=BUDGET (uniform across block).
            float nlo = lo, nhi = hi;
            bool crossed = false;
            #pragma unroll
            for (int c = 0; c < 7; c++) {
                float tc = lo + (c + 1) * step;
                if (!crossed) {
                    if (sh_tot[c] > BUDGETF) nlo = tc;
                    else { nhi = tc; crossed = true; }
                }
            }
            lo = nlo; hi = nhi;
            __syncthreads();   // protect redf/sh_tot before next round
        }
        tau = 0.5f * (lo + hi);
    }
    if (tid == 0) d_tau[b] = tau;
}

// ---------------------------------------------------------------------------
// Kernel 3b: scatter — out[b,p] = 1 (p<qe) | clip01(s[idx]-tau) | 0.
// Grid (8, 64): fully parallel, coalesced shifted reads of d_s through L2.
// ---------------------------------------------------------------------------
__global__ void __launch_bounds__(512) scatter_kernel(const int* __restrict__ qe_arr,
                                                      float* __restrict__ out) {
    int b = blockIdx.y;
    int p = blockIdx.x * 512 + threadIdx.x;
    int qe = qe_arr[b];
    int clen = d_len[b] - 1;
    float tau = d_tau[b];

    float r;
    if (p < qe) {
        r = 1.f;
    } else {
        int idx = p - qe + 1;                 // >= 1
        r = (idx <= clen) ? clip01(d_s[b * LC + idx] - tau) : 0.f;
    }
    out[b * LC + p] = r;
}

// ---------------------------------------------------------------------------
extern "C" void kernel_launch(void* const* d_in, const int* in_sizes, int n_in,
                              void* d_out, int out_size) {
    const float* question = (const float*)d_in[0];  // [B,1,H]
    const float* context  = (const float*)d_in[1];  // [B,LC,H]
    const float* Wq       = (const float*)d_in[2];  // [H,P]
    const float* bq       = (const float*)d_in[3];  // [P]
    const float* Wc       = (const float*)d_in[4];  // [H,P]
    const float* bc       = (const float*)d_in[5];  // [P]
    const int*   maskp    = (const int*)d_in[6];    // [B,LC]
    const int*   qep      = (const int*)d_in[7];    // [B]
    float* out = (float*)d_out;                     // [B,MAXLEN]

    qproj_kernel<<<NB, 512>>>(question, Wq, bq, bc, maskp);
    dim3 gu(NB, 4);
    uproj_kernel<<<gu, 256>>>(Wc);
    score_kernel<<<SCORE_BLOCKS, 256>>>(context);
    tau_kernel<<<NB, 512>>>();
    dim3 gs(LC / 512, NB);
    scatter_kernel<<<gs, 512>>>(qep, out);
}